// round 6
// baseline (speedup 1.0000x reference)
#include <cuda_runtime.h>
#include <math.h>

#define KK 128
#define ADIM 64
#define LDUR 6
#define TT 60
#define BSZ 1024
#define TH2 1024
#define NEGINF -1e38f

// ---------------- scratch (static device, no allocations) ----------------
__device__ float g_h[(size_t)BSZ * (KK * ADIM)];          // 1024 x 8192  (32 MB)
__device__ float g_cond[(size_t)BSZ * (KK * ADIM * 2)];   // 1024 x 16384 (64 MB)
__device__ float g_pi[BSZ * KK];                          // 512 KB
__device__ float g_tsc[KK * KK];                          // 64 KB
__device__ float g_P[(size_t)BSZ * KK * KK];              // 64 MB

// ---------------- pi = log_softmax(uniqenc @ W_init + b) ----------------
__global__ __launch_bounds__(128) void pi_kernel(
    const float* __restrict__ uniq, const float* __restrict__ W,
    const float* __restrict__ b, float* __restrict__ pi)
{
    __shared__ float u[TH2];
    __shared__ float red[128];
    int bidx = blockIdx.x, k = threadIdx.x;
    for (int i = k; i < TH2; i += 128) u[i] = uniq[bidx * TH2 + i];
    __syncthreads();
    float acc = 0.f;
#pragma unroll 8
    for (int i = 0; i < TH2; i++) acc += u[i] * W[i * KK + k];
    acc += b[k];
    // block log-softmax over 128
    red[k] = acc; __syncthreads();
    for (int s = 64; s > 0; s >>= 1) { if (k < s) red[k] = fmaxf(red[k], red[k + s]); __syncthreads(); }
    float m = red[0]; __syncthreads();
    float e = expf(acc - m);
    red[k] = e; __syncthreads();
    for (int s = 64; s > 0; s >>= 1) { if (k < s) red[k] += red[k + s]; __syncthreads(); }
    float ssum = red[0];
    pi[bidx * KK + k] = acc - m - logf(ssum);
}

// ---------------- tscores = A_from @ A_to + diag(NEGINF) ----------------
__global__ __launch_bounds__(128) void tsc_kernel(
    const float* __restrict__ Af, const float* __restrict__ At, float* __restrict__ tsc)
{
    int k = blockIdx.x, j = threadIdx.x;
    float acc = 0.f;
#pragma unroll
    for (int a = 0; a < ADIM; a++) acc += Af[k * ADIM + a] * At[a * KK + j];
    if (k == j) acc += NEGINF;
    tsc[k * KK + j] = acc;
}

// ---------------- tiled fp32 GEMM: C = op(A @ B + bias) ----------------
// A: MxKd row-major, B: KdxN row-major. BM=BN=128, BK=8, 256 threads, 8x8 tiles.
__global__ __launch_bounds__(256) void sgemm_kernel(
    const float* __restrict__ A, const float* __restrict__ B,
    const float* __restrict__ bias, float* __restrict__ C,
    int M, int N, int Kd, int do_relu)
{
    const int BM = 128, BN = 128, BK = 8;
    __shared__ float As[BK][BM];
    __shared__ float Bs[BK][BN];
    int tid = threadIdx.x;
    int tx = tid & 15, ty = tid >> 4;
    int m0 = blockIdx.y * BM, n0 = blockIdx.x * BN;
    float acc[8][8];
#pragma unroll
    for (int i = 0; i < 8; i++)
#pragma unroll
        for (int j = 0; j < 8; j++) acc[i][j] = 0.f;

    int arow = tid >> 1;            // 0..127
    int acol = (tid & 1) * 4;       // 0 or 4
    int brow = tid >> 5;            // 0..7
    int bcol = (tid & 31) * 4;      // 0..124
    const float* Aptr = A + (size_t)(m0 + arow) * Kd + acol;
    const float* Bptr = B + (size_t)brow * N + (n0 + bcol);

    for (int k0 = 0; k0 < Kd; k0 += BK) {
        float4 av = *(const float4*)(Aptr);
        float4 bv = *(const float4*)(Bptr);
        As[acol + 0][arow] = av.x;
        As[acol + 1][arow] = av.y;
        As[acol + 2][arow] = av.z;
        As[acol + 3][arow] = av.w;
        *(float4*)&Bs[brow][bcol] = bv;
        __syncthreads();
#pragma unroll
        for (int kk = 0; kk < BK; kk++) {
            float ra[8], rb[8];
            float4 a0 = *(const float4*)&As[kk][ty * 8];
            float4 a1 = *(const float4*)&As[kk][ty * 8 + 4];
            float4 b0 = *(const float4*)&Bs[kk][tx * 8];
            float4 b1 = *(const float4*)&Bs[kk][tx * 8 + 4];
            ra[0]=a0.x; ra[1]=a0.y; ra[2]=a0.z; ra[3]=a0.w; ra[4]=a1.x; ra[5]=a1.y; ra[6]=a1.z; ra[7]=a1.w;
            rb[0]=b0.x; rb[1]=b0.y; rb[2]=b0.z; rb[3]=b0.w; rb[4]=b1.x; rb[5]=b1.y; rb[6]=b1.z; rb[7]=b1.w;
#pragma unroll
            for (int i = 0; i < 8; i++)
#pragma unroll
                for (int j = 0; j < 8; j++) acc[i][j] += ra[i] * rb[j];
        }
        __syncthreads();
        Aptr += BK;
        Bptr += (size_t)BK * N;
    }
#pragma unroll
    for (int i = 0; i < 8; i++) {
        int m = m0 + ty * 8 + i;
#pragma unroll
        for (int j4 = 0; j4 < 2; j4++) {
            int n = n0 + tx * 8 + j4 * 4;
            float4 v;
            v.x = acc[i][j4 * 4 + 0] + bias[n + 0];
            v.y = acc[i][j4 * 4 + 1] + bias[n + 1];
            v.z = acc[i][j4 * 4 + 2] + bias[n + 2];
            v.w = acc[i][j4 * 4 + 3] + bias[n + 3];
            if (do_relu) {
                v.x = fmaxf(v.x, 0.f); v.y = fmaxf(v.y, 0.f);
                v.z = fmaxf(v.z, 0.f); v.w = fmaxf(v.w, 0.f);
            }
            *(float4*)&C[(size_t)m * N + n] = v;
        }
    }
}

// ---------------- trans: P[b,k,j] = softmax_j(tsc[k,j] + from[b,k,:].to[b,j,:]) ----------------
// Dynamic smem: 64 KB. Phase 1 uses it as fr/to staging (2*128*64 floats);
// phase 2 reuses the SAME region as the 128x128 score tile (accumulators are
// in registers across the boundary).
__global__ __launch_bounds__(256) void trans_kernel(
    const float* __restrict__ cond, const float* __restrict__ tsc, float* __restrict__ P)
{
    extern __shared__ float sm[];
    float* fr = sm;                      // 128*64
    float* to = sm + KK * ADIM;          // 128*64
    float* tr = sm;                      // 128*128 (aliases fr/to after phase 1)
    int b = blockIdx.x, tid = threadIdx.x;
    const float* cb = cond + (size_t)b * KK * 2 * ADIM;
    for (int idx = tid; idx < KK * 2 * ADIM; idx += 256) {
        int kk = idx >> 7;
        int a = idx & 127;
        float v = cb[idx];
        if (a < ADIM) fr[kk * ADIM + a] = v;
        else          to[kk * ADIM + (a - ADIM)] = v;
    }
    __syncthreads();
    int tx = tid & 15, ty = tid >> 4;
    float acc[8][8];
#pragma unroll
    for (int i = 0; i < 8; i++)
#pragma unroll
        for (int j = 0; j < 8; j++) acc[i][j] = 0.f;
#pragma unroll 4
    for (int a = 0; a < ADIM; a++) {
        float ra[8], rb[8];
#pragma unroll
        for (int i = 0; i < 8; i++) ra[i] = fr[(ty * 8 + i) * ADIM + a];
#pragma unroll
        for (int j = 0; j < 8; j++) rb[j] = to[(tx * 8 + j) * ADIM + a];
#pragma unroll
        for (int i = 0; i < 8; i++)
#pragma unroll
            for (int j = 0; j < 8; j++) acc[i][j] += ra[i] * rb[j];
    }
    __syncthreads();   // phase boundary: fr/to dead, tr takes over the buffer
#pragma unroll
    for (int i = 0; i < 8; i++) {
        int row = ty * 8 + i;
#pragma unroll
        for (int j = 0; j < 8; j++) {
            int col = tx * 8 + j;
            tr[row * KK + col] = acc[i][j] + tsc[row * KK + col];
        }
    }
    __syncthreads();
    // row softmax -> write probabilities
    int wid = tid >> 5, lane = tid & 31;
    for (int row = wid; row < KK; row += 8) {
        float v[4]; float m = -INFINITY;
#pragma unroll
        for (int i = 0; i < 4; i++) { v[i] = tr[row * KK + lane + i * 32]; m = fmaxf(m, v[i]); }
#pragma unroll
        for (int off = 16; off; off >>= 1) m = fmaxf(m, __shfl_xor_sync(0xffffffffu, m, off));
        float e[4]; float s = 0.f;
#pragma unroll
        for (int i = 0; i < 4; i++) { e[i] = expf(v[i] - m); s += e[i]; }
#pragma unroll
        for (int off = 16; off; off >>= 1) s += __shfl_xor_sync(0xffffffffu, s, off);
        float inv = 1.0f / s;
#pragma unroll
        for (int i = 0; i < 4; i++)
            P[(size_t)b * KK * KK + row * KK + lane + i * 32] = e[i] * inv;
    }
}

// ---------------- scan: per-batch-element forward recurrence ----------------
__global__ __launch_bounds__(128) void scan_kernel(
    const float* __restrict__ obs, const float* __restrict__ pi,
    const float* __restrict__ Pg, float* __restrict__ out)
{
    extern __shared__ float sm[];
    float* Psm  = sm;                 // 128*128
    float* buf  = sm + KK * KK;       // 6*128
    float* pvec = buf + LDUR * KK;    // 128
    float* red  = pvec + KK;          // 128
    int b = blockIdx.x, j = threadIdx.x;
    const float len_lp = -1.7917594692280550f;   // -log(6)

    // load P[b] (64 KB, coalesced float4)
    {
        const float4* src = (const float4*)(Pg + (size_t)b * KK * KK);
        float4* dst = (float4*)Psm;
        for (int i = j; i < KK * KK / 4; i += 128) dst[i] = src[i];
    }
    buf[0 * KK + j] = pi[b * KK + j];
#pragma unroll
    for (int l = 1; l < LDUR; l++) buf[l * KK + j] = NEGINF;
    __syncthreads();

    int base = 0;
    for (int t = 0; t < TT; t++) {
        // alpha_j = LSE_l( buf[l][j] + obs_seg(t,l)[j] + len_lp )
        float vs[LDUR];
        float vmax = -INFINITY;
#pragma unroll
        for (int l = 0; l < LDUR; l++) {
            int st = t - l;
            float v;
            if (st >= 0) {
                float o = obs[(((size_t)l * TT + st) * BSZ + b) * KK + j];
                v = buf[((base + l) % LDUR) * KK + j] + o + len_lp;
            } else {
                v = NEGINF;
            }
            vs[l] = v;
            vmax = fmaxf(vmax, v);
        }
        float alpha;
        if (vmax < -1e30f) alpha = NEGINF;
        else {
            float s = 0.f;
#pragma unroll
            for (int l = 0; l < LDUR; l++) s += expf(vs[l] - vmax);
            alpha = vmax + logf(s);
        }
        // block max of alpha
        red[j] = alpha; __syncthreads();
        for (int s2 = 64; s2; s2 >>= 1) { if (j < s2) red[j] = fmaxf(red[j], red[j + s2]); __syncthreads(); }
        float M = red[0];
        __syncthreads();
        pvec[j] = expf(alpha - M);
        __syncthreads();

        if (t == TT - 1) {
            // out[b] = LSE_j alpha = M + log(sum pvec)
            red[j] = pvec[j]; __syncthreads();
            for (int s2 = 64; s2; s2 >>= 1) { if (j < s2) red[j] += red[j + s2]; __syncthreads(); }
            if (j == 0) out[b] = M + logf(red[0]);
            break;
        }

        // astar_j = M + log( sum_k pvec[k] * P[k][j] )
        float a0 = 0.f, a1 = 0.f, a2 = 0.f, a3 = 0.f;
#pragma unroll 8
        for (int kk = 0; kk < KK; kk += 4) {
            a0 += pvec[kk + 0] * Psm[(kk + 0) * KK + j];
            a1 += pvec[kk + 1] * Psm[(kk + 1) * KK + j];
            a2 += pvec[kk + 2] * Psm[(kk + 2) * KK + j];
            a3 += pvec[kk + 3] * Psm[(kk + 3) * KK + j];
        }
        float astar = M + logf((a0 + a1) + (a2 + a3));

        base = (base + LDUR - 1) % LDUR;
        buf[base * KK + j] = astar;
        __syncthreads();
    }
}

// ---------------- launch ----------------
extern "C" void kernel_launch(void* const* d_in, const int* in_sizes, int n_in,
                              void* d_out, int out_size)
{
    const float* uniqenc = (const float*)d_in[0];
    const float* obs_lps = (const float*)d_in[1];
    const float* W_init  = (const float*)d_in[2];
    const float* b_init  = (const float*)d_in[3];
    const float* A_from  = (const float*)d_in[4];
    const float* A_to    = (const float*)d_in[5];
    const float* W_c1    = (const float*)d_in[6];
    const float* b_c1    = (const float*)d_in[7];
    const float* W_c2    = (const float*)d_in[8];
    const float* b_c2    = (const float*)d_in[9];
    float* out = (float*)d_out;

    float *p_h, *p_cond, *p_pi, *p_tsc, *p_P;
    cudaGetSymbolAddress((void**)&p_h, g_h);
    cudaGetSymbolAddress((void**)&p_cond, g_cond);
    cudaGetSymbolAddress((void**)&p_pi, g_pi);
    cudaGetSymbolAddress((void**)&p_tsc, g_tsc);
    cudaGetSymbolAddress((void**)&p_P, g_P);

    // capture-safe, called every time (no static guards per harness rules)
    cudaFuncSetAttribute(trans_kernel, cudaFuncAttributeMaxDynamicSharedMemorySize,
                         (2 * KK * ADIM) * (int)sizeof(float));
    cudaFuncSetAttribute(scan_kernel, cudaFuncAttributeMaxDynamicSharedMemorySize,
                         (KK * KK + LDUR * KK + 2 * KK) * (int)sizeof(float));

    // pi (independent)
    pi_kernel<<<BSZ, 128>>>(uniqenc, W_init, b_init, p_pi);
    // tscores (independent)
    tsc_kernel<<<KK, 128>>>(A_from, A_to, p_tsc);
    // h = relu(uniqenc @ W_c1 + b_c1):  1024 x 8192, Kd=1024
    {
        dim3 grid(8192 / 128, 1024 / 128);
        sgemm_kernel<<<grid, 256>>>(uniqenc, W_c1, b_c1, p_h, 1024, 8192, 1024, 1);
    }
    // cond = h @ W_c2 + b_c2:  1024 x 16384, Kd=8192
    {
        dim3 grid(16384 / 128, 1024 / 128);
        sgemm_kernel<<<grid, 256>>>(p_h, W_c2, b_c2, p_cond, 1024, 16384, 8192, 0);
    }
    // trans -> P
    trans_kernel<<<BSZ, 256, (2 * KK * ADIM) * sizeof(float)>>>(p_cond, p_tsc, p_P);
    // scan
    scan_kernel<<<BSZ, 128, (KK * KK + LDUR * KK + 2 * KK) * sizeof(float)>>>(obs_lps, p_pi, p_P, out);

    (void)in_sizes; (void)n_in; (void)out_size;
}

// round 15
// speedup vs baseline: 3.2962x; 3.2962x over previous
#include <cuda_runtime.h>
#include <cuda_bf16.h>
#include <math.h>
#include <stdint.h>

#define KK 128
#define ADIM 64
#define LDUR 6
#define TT 60
#define BSZ 1024
#define TH2 1024
#define NEGINF -1e38f

// ---- HMMA GEMM tiling ----
#define BM 128
#define BN 128
#define BKT 32            // k per stage (bf16 elems)
#define ROWB 80           // padded smem row bytes (32 halves -> 40 halves)
#define MATB (BM * ROWB)  // 10240 bytes per matrix tile
#define STGB (4 * MATB)   // Ah, Al, Bh, Bl
#define NSTG 3
#define GEMM_SMEM (NSTG * STGB)   // 122880

// ---------------- scratch (static device, no allocations) ----------------
__device__ __align__(16) __nv_bfloat16 g_uh[(size_t)BSZ * TH2];
__device__ __align__(16) __nv_bfloat16 g_ul[(size_t)BSZ * TH2];
__device__ __align__(16) __nv_bfloat16 g_w1h[(size_t)8192 * 1024];
__device__ __align__(16) __nv_bfloat16 g_w1l[(size_t)8192 * 1024];
__device__ __align__(16) __nv_bfloat16 g_w2h[(size_t)16384 * 8192];
__device__ __align__(16) __nv_bfloat16 g_w2l[(size_t)16384 * 8192];
__device__ __align__(16) __nv_bfloat16 g_hh[(size_t)BSZ * 8192];
__device__ __align__(16) __nv_bfloat16 g_hl[(size_t)BSZ * 8192];
__device__ float g_cond[(size_t)BSZ * (KK * ADIM * 2)];
__device__ float g_pi[BSZ * KK];
__device__ float g_tsc[KK * KK];
__device__ float g_P[(size_t)BSZ * KK * KK];

__device__ __forceinline__ uint32_t smem_u32(const void* p) {
    uint32_t a;
    asm("{ .reg .u64 t; cvta.to.shared.u64 t, %1; cvt.u32.u64 %0, t; }" : "=r"(a) : "l"(p));
    return a;
}
#define CPASYNC16(sa, ga) \
    asm volatile("cp.async.cg.shared.global [%0], [%1], 16;" :: "r"(sa), "l"(ga) : "memory")
#define CPCOMMIT() asm volatile("cp.async.commit_group;" ::: "memory")
#define CPWAIT1()  asm volatile("cp.async.wait_group 1;" ::: "memory")

__device__ __forceinline__ void ldsm4(uint32_t* r, uint32_t a) {
    asm volatile("ldmatrix.sync.aligned.m8n8.x4.shared.b16 {%0,%1,%2,%3}, [%4];"
        : "=r"(r[0]), "=r"(r[1]), "=r"(r[2]), "=r"(r[3]) : "r"(a));
}
__device__ __forceinline__ void mma16816(float* d, const uint32_t* a, const uint32_t* b) {
    asm volatile("mma.sync.aligned.m16n8k16.row.col.f32.bf16.bf16.f32 "
        "{%0,%1,%2,%3}, {%4,%5,%6,%7}, {%8,%9}, {%0,%1,%2,%3};"
        : "+f"(d[0]), "+f"(d[1]), "+f"(d[2]), "+f"(d[3])
        : "r"(a[0]), "r"(a[1]), "r"(a[2]), "r"(a[3]), "r"(b[0]), "r"(b[1]));
}

// ---------------- split / transpose-split prep ----------------
__global__ __launch_bounds__(256) void split_kernel(
    const float* __restrict__ in, __nv_bfloat16* __restrict__ hi,
    __nv_bfloat16* __restrict__ lo, size_t n)
{
    size_t i = (size_t)blockIdx.x * 256 + threadIdx.x;
    size_t st = (size_t)gridDim.x * 256;
    for (; i < n; i += st) {
        float v = in[i];
        __nv_bfloat16 h = __float2bfloat16_rn(v);
        hi[i] = h;
        lo[i] = __float2bfloat16_rn(v - __bfloat162float(h));
    }
}

__global__ __launch_bounds__(256) void transpose_split_kernel(
    const float* __restrict__ in, __nv_bfloat16* __restrict__ hi,
    __nv_bfloat16* __restrict__ lo, int R, int C)
{
    __shared__ float t[64][65];
    int tx = threadIdx.x & 63, ty = threadIdx.x >> 6;
    int c0 = blockIdx.x * 64, r0 = blockIdx.y * 64;
    for (int r = ty; r < 64; r += 4) t[r][tx] = in[(size_t)(r0 + r) * C + c0 + tx];
    __syncthreads();
    for (int r = ty; r < 64; r += 4) {
        float v = t[tx][r];
        __nv_bfloat16 h = __float2bfloat16_rn(v);
        size_t o = (size_t)(c0 + r) * R + r0 + tx;
        hi[o] = h;
        lo[o] = __float2bfloat16_rn(v - __bfloat162float(h));
    }
}

// ---------------- HMMA GEMM: D[M,N] = A @ B^T, 3-pass bf16 hi/lo split ----------------
// A (hi/lo): [M][Kd] row-major bf16.  B (hi/lo): [N][Kd] row-major bf16 (i.e. W^T).
// grid = (M/128, N/128), 256 threads. relu_split: out = relu(D+bias) -> hi/lo bf16.
__global__ __launch_bounds__(256, 1) void mm_kernel(
    const __nv_bfloat16* __restrict__ Agh, const __nv_bfloat16* __restrict__ Agl,
    const __nv_bfloat16* __restrict__ Bgh, const __nv_bfloat16* __restrict__ Bgl,
    const float* __restrict__ bias, float* __restrict__ out_f32,
    __nv_bfloat16* __restrict__ out_hi, __nv_bfloat16* __restrict__ out_lo,
    int Nout, int Kd, int relu_split)
{
    extern __shared__ __align__(16) char smem[];
    const uint32_t sb0 = smem_u32(smem);
    const int tid = threadIdx.x, lane = tid & 31, wid = tid >> 5;
    const int wm = wid >> 1, wn = wid & 1;
    const int m0 = blockIdx.x * BM, n0 = blockIdx.y * BN;
    const int NC = Kd / BKT;

    const __nv_bfloat16* pAh = Agh + (size_t)m0 * Kd;
    const __nv_bfloat16* pAl = Agl + (size_t)m0 * Kd;
    const __nv_bfloat16* pBh = Bgh + (size_t)n0 * Kd;
    const __nv_bfloat16* pBl = Bgl + (size_t)n0 * Kd;

    const int li0 = tid * 2;

    auto load_stage = [&](int c) {
        uint32_t sb = sb0 + (c % NSTG) * STGB;
        int k0 = c * BKT;
#pragma unroll
        for (int ii = 0; ii < 2; ii++) {
            int i = li0 + ii;
            int row = i >> 2, ch = i & 3;
            size_t go = (size_t)row * Kd + k0 + ch * 8;
            uint32_t so = (uint32_t)(row * ROWB + ch * 16);
            CPASYNC16(sb + so,            pAh + go);
            CPASYNC16(sb + MATB + so,     pAl + go);
            CPASYNC16(sb + 2 * MATB + so, pBh + go);
            CPASYNC16(sb + 3 * MATB + so, pBl + go);
        }
    };

    float acc[2][8][4];
#pragma unroll
    for (int mt = 0; mt < 2; mt++)
#pragma unroll
        for (int nt = 0; nt < 8; nt++)
#pragma unroll
            for (int r = 0; r < 4; r++) acc[mt][nt][r] = 0.f;

    // lane-level smem offsets for ldmatrix
    // A: x4 -> matrices (rows0-7,k0-7),(rows8-15,k0-7),(rows0-7,k8-15),(rows8-15,k8-15)
    const uint32_t aoff = (uint32_t)((wm * 32 + (lane & 15)) * ROWB + (lane >> 4) * 16);
    // B (non-trans): addresses point at n-rows; matrices (n0-7,k0-7),(n0-7,k8-15),(n8-15,k0-7),(n8-15,k8-15)
    const uint32_t boff = (uint32_t)((wn * 64 + (lane & 7) + ((lane >> 4) & 1) * 8) * ROWB
                                     + ((lane >> 3) & 1) * 16);

    load_stage(0); CPCOMMIT();
    load_stage(1); CPCOMMIT();
    CPWAIT1();
    __syncthreads();

    for (int c = 0; c < NC; c++) {
        if (c + 2 < NC) load_stage(c + 2);
        CPCOMMIT();

        uint32_t sb = sb0 + (c % NSTG) * STGB;
#pragma unroll
        for (int kk = 0; kk < 2; kk++) {
            uint32_t ah[2][4], al[2][4], bh[8][2], bl[8][2];
#pragma unroll
            for (int mt = 0; mt < 2; mt++) {
                ldsm4(ah[mt], sb + aoff + mt * (16 * ROWB) + kk * 32);
                ldsm4(al[mt], sb + MATB + aoff + mt * (16 * ROWB) + kk * 32);
            }
#pragma unroll
            for (int np = 0; np < 4; np++) {
                uint32_t r[4];
                ldsm4(r, sb + 2 * MATB + boff + np * (16 * ROWB) + kk * 32);
                bh[2 * np][0] = r[0]; bh[2 * np][1] = r[1];
                bh[2 * np + 1][0] = r[2]; bh[2 * np + 1][1] = r[3];
                ldsm4(r, sb + 3 * MATB + boff + np * (16 * ROWB) + kk * 32);
                bl[2 * np][0] = r[0]; bl[2 * np][1] = r[1];
                bl[2 * np + 1][0] = r[2]; bl[2 * np + 1][1] = r[3];
            }
#pragma unroll
            for (int mt = 0; mt < 2; mt++)
#pragma unroll
                for (int nt = 0; nt < 8; nt++) {
                    mma16816(acc[mt][nt], ah[mt], bh[nt]);
                    mma16816(acc[mt][nt], al[mt], bh[nt]);
                    mma16816(acc[mt][nt], ah[mt], bl[nt]);
                }
        }
        CPWAIT1();
        __syncthreads();
    }

    // epilogue
#pragma unroll
    for (int mt = 0; mt < 2; mt++) {
        int mrow = m0 + wm * 32 + mt * 16 + (lane >> 2);
#pragma unroll
        for (int nt = 0; nt < 8; nt++) {
            int n = n0 + wn * 64 + nt * 8 + (lane & 3) * 2;
            float b0 = bias[n], b1 = bias[n + 1];
            float v0 = acc[mt][nt][0] + b0, v1 = acc[mt][nt][1] + b1;
            float v2 = acc[mt][nt][2] + b0, v3 = acc[mt][nt][3] + b1;
            if (!relu_split) {
                *(float2*)(out_f32 + (size_t)mrow * Nout + n)       = make_float2(v0, v1);
                *(float2*)(out_f32 + (size_t)(mrow + 8) * Nout + n) = make_float2(v2, v3);
            } else {
                v0 = fmaxf(v0, 0.f); v1 = fmaxf(v1, 0.f);
                v2 = fmaxf(v2, 0.f); v3 = fmaxf(v3, 0.f);
                __nv_bfloat16 h0 = __float2bfloat16_rn(v0), h1 = __float2bfloat16_rn(v1);
                __nv_bfloat16 h2 = __float2bfloat16_rn(v2), h3 = __float2bfloat16_rn(v3);
                __nv_bfloat162 hv0; hv0.x = h0; hv0.y = h1;
                __nv_bfloat162 hv1; hv1.x = h2; hv1.y = h3;
                __nv_bfloat162 lv0, lv1;
                lv0.x = __float2bfloat16_rn(v0 - __bfloat162float(h0));
                lv0.y = __float2bfloat16_rn(v1 - __bfloat162float(h1));
                lv1.x = __float2bfloat16_rn(v2 - __bfloat162float(h2));
                lv1.y = __float2bfloat16_rn(v3 - __bfloat162float(h3));
                *(__nv_bfloat162*)(out_hi + (size_t)mrow * Nout + n)       = hv0;
                *(__nv_bfloat162*)(out_lo + (size_t)mrow * Nout + n)       = lv0;
                *(__nv_bfloat162*)(out_hi + (size_t)(mrow + 8) * Nout + n) = hv1;
                *(__nv_bfloat162*)(out_lo + (size_t)(mrow + 8) * Nout + n) = lv1;
            }
        }
    }
}

// ---------------- pi = log_softmax(uniqenc @ W_init + b) ----------------
__global__ __launch_bounds__(128) void pi_kernel(
    const float* __restrict__ uniq, const float* __restrict__ W,
    const float* __restrict__ b, float* __restrict__ pi)
{
    __shared__ float u[TH2];
    __shared__ float red[128];
    int bidx = blockIdx.x, k = threadIdx.x;
    for (int i = k; i < TH2; i += 128) u[i] = uniq[bidx * TH2 + i];
    __syncthreads();
    float acc = 0.f;
#pragma unroll 8
    for (int i = 0; i < TH2; i++) acc += u[i] * W[i * KK + k];
    acc += b[k];
    red[k] = acc; __syncthreads();
    for (int s = 64; s > 0; s >>= 1) { if (k < s) red[k] = fmaxf(red[k], red[k + s]); __syncthreads(); }
    float m = red[0]; __syncthreads();
    float e = expf(acc - m);
    red[k] = e; __syncthreads();
    for (int s = 64; s > 0; s >>= 1) { if (k < s) red[k] += red[k + s]; __syncthreads(); }
    pi[bidx * KK + k] = acc - m - logf(red[0]);
}

__global__ __launch_bounds__(128) void tsc_kernel(
    const float* __restrict__ Af, const float* __restrict__ At, float* __restrict__ tsc)
{
    int k = blockIdx.x, j = threadIdx.x;
    float acc = 0.f;
#pragma unroll
    for (int a = 0; a < ADIM; a++) acc += Af[k * ADIM + a] * At[a * KK + j];
    if (k == j) acc += NEGINF;
    tsc[k * KK + j] = acc;
}

// ---------------- trans -> P (softmax probabilities) ----------------
__global__ __launch_bounds__(256) void trans_kernel(
    const float* __restrict__ cond, const float* __restrict__ tsc, float* __restrict__ P)
{
    extern __shared__ float sm[];
    float* fr = sm;
    float* to = sm + KK * ADIM;
    float* tr = sm;
    int b = blockIdx.x, tid = threadIdx.x;
    const float* cb = cond + (size_t)b * KK * 2 * ADIM;
    for (int idx = tid; idx < KK * 2 * ADIM; idx += 256) {
        int kk = idx >> 7, a = idx & 127;
        float v = cb[idx];
        if (a < ADIM) fr[kk * ADIM + a] = v;
        else          to[kk * ADIM + (a - ADIM)] = v;
    }
    __syncthreads();
    int tx = tid & 15, ty = tid >> 4;
    float acc[8][8];
#pragma unroll
    for (int i = 0; i < 8; i++)
#pragma unroll
        for (int j = 0; j < 8; j++) acc[i][j] = 0.f;
#pragma unroll 4
    for (int a = 0; a < ADIM; a++) {
        float ra[8], rb[8];
#pragma unroll
        for (int i = 0; i < 8; i++) ra[i] = fr[(ty * 8 + i) * ADIM + a];
#pragma unroll
        for (int j = 0; j < 8; j++) rb[j] = to[(tx * 8 + j) * ADIM + a];
#pragma unroll
        for (int i = 0; i < 8; i++)
#pragma unroll
            for (int j = 0; j < 8; j++) acc[i][j] += ra[i] * rb[j];
    }
    __syncthreads();
#pragma unroll
    for (int i = 0; i < 8; i++)
#pragma unroll
        for (int j = 0; j < 8; j++)
            tr[(ty * 8 + i) * KK + tx * 8 + j] = acc[i][j] + tsc[(ty * 8 + i) * KK + tx * 8 + j];
    __syncthreads();
    int wid = tid >> 5, lane = tid & 31;
    for (int row = wid; row < KK; row += 8) {
        float v[4]; float m = -INFINITY;
#pragma unroll
        for (int i = 0; i < 4; i++) { v[i] = tr[row * KK + lane + i * 32]; m = fmaxf(m, v[i]); }
#pragma unroll
        for (int off = 16; off; off >>= 1) m = fmaxf(m, __shfl_xor_sync(0xffffffffu, m, off));
        float e[4]; float s = 0.f;
#pragma unroll
        for (int i = 0; i < 4; i++) { e[i] = expf(v[i] - m); s += e[i]; }
#pragma unroll
        for (int off = 16; off; off >>= 1) s += __shfl_xor_sync(0xffffffffu, s, off);
        float inv = 1.0f / s;
#pragma unroll
        for (int i = 0; i < 4; i++)
            P[(size_t)b * KK * KK + row * KK + lane + i * 32] = e[i] * inv;
    }
}

// ---------------- scan ----------------
__global__ __launch_bounds__(128) void scan_kernel(
    const float* __restrict__ obs, const float* __restrict__ pi,
    const float* __restrict__ Pg, float* __restrict__ out)
{
    extern __shared__ float sm[];
    float* Psm  = sm;
    float* buf  = sm + KK * KK;
    float* pvec = buf + LDUR * KK;
    float* red  = pvec + KK;
    int b = blockIdx.x, j = threadIdx.x;
    const float len_lp = -1.7917594692280550f;
    {
        const float4* src = (const float4*)(Pg + (size_t)b * KK * KK);
        float4* dst = (float4*)Psm;
        for (int i = j; i < KK * KK / 4; i += 128) dst[i] = src[i];
    }
    buf[j] = pi[b * KK + j];
#pragma unroll
    for (int l = 1; l < LDUR; l++) buf[l * KK + j] = NEGINF;
    __syncthreads();
    int base = 0;
    for (int t = 0; t < TT; t++) {
        float vs[LDUR], vmax = -INFINITY;
#pragma unroll
        for (int l = 0; l < LDUR; l++) {
            int st = t - l;
            float v = NEGINF;
            if (st >= 0)
                v = buf[((base + l) % LDUR) * KK + j] + obs[(((size_t)l * TT + st) * BSZ + b) * KK + j] + len_lp;
            vs[l] = v; vmax = fmaxf(vmax, v);
        }
        float alpha;
        if (vmax < -1e30f) alpha = NEGINF;
        else {
            float s = 0.f;
#pragma unroll
            for (int l = 0; l < LDUR; l++) s += expf(vs[l] - vmax);
            alpha = vmax + logf(s);
        }
        red[j] = alpha; __syncthreads();
        for (int s2 = 64; s2; s2 >>= 1) { if (j < s2) red[j] = fmaxf(red[j], red[j + s2]); __syncthreads(); }
        float M = red[0];
        __syncthreads();
        pvec[j] = expf(alpha - M);
        __syncthreads();
        if (t == TT - 1) {
            red[j] = pvec[j]; __syncthreads();
            for (int s2 = 64; s2; s2 >>= 1) { if (j < s2) red[j] += red[j + s2]; __syncthreads(); }
            if (j == 0) out[b] = M + logf(red[0]);
            break;
        }
        float a0 = 0.f, a1 = 0.f, a2 = 0.f, a3 = 0.f;
#pragma unroll 8
        for (int kk = 0; kk < KK; kk += 4) {
            a0 += pvec[kk + 0] * Psm[(kk + 0) * KK + j];
            a1 += pvec[kk + 1] * Psm[(kk + 1) * KK + j];
            a2 += pvec[kk + 2] * Psm[(kk + 2) * KK + j];
            a3 += pvec[kk + 3] * Psm[(kk + 3) * KK + j];
        }
        float astar = M + logf((a0 + a1) + (a2 + a3));
        base = (base + LDUR - 1) % LDUR;
        buf[base * KK + j] = astar;
        __syncthreads();
    }
}

// ---------------- launch ----------------
extern "C" void kernel_launch(void* const* d_in, const int* in_sizes, int n_in,
                              void* d_out, int out_size)
{
    const float* uniqenc = (const float*)d_in[0];
    const float* obs_lps = (const float*)d_in[1];
    const float* W_init  = (const float*)d_in[2];
    const float* b_init  = (const float*)d_in[3];
    const float* A_from  = (const float*)d_in[4];
    const float* A_to    = (const float*)d_in[5];
    const float* W_c1    = (const float*)d_in[6];
    const float* b_c1    = (const float*)d_in[7];
    const float* W_c2    = (const float*)d_in[8];
    const float* b_c2    = (const float*)d_in[9];
    float* out = (float*)d_out;

    void *p_uh, *p_ul, *p_w1h, *p_w1l, *p_w2h, *p_w2l, *p_hh, *p_hl;
    float *p_cond, *p_pi, *p_tsc, *p_P;
    cudaGetSymbolAddress(&p_uh, g_uh);   cudaGetSymbolAddress(&p_ul, g_ul);
    cudaGetSymbolAddress(&p_w1h, g_w1h); cudaGetSymbolAddress(&p_w1l, g_w1l);
    cudaGetSymbolAddress(&p_w2h, g_w2h); cudaGetSymbolAddress(&p_w2l, g_w2l);
    cudaGetSymbolAddress(&p_hh, g_hh);   cudaGetSymbolAddress(&p_hl, g_hl);
    cudaGetSymbolAddress((void**)&p_cond, g_cond);
    cudaGetSymbolAddress((void**)&p_pi, g_pi);
    cudaGetSymbolAddress((void**)&p_tsc, g_tsc);
    cudaGetSymbolAddress((void**)&p_P, g_P);

    cudaFuncSetAttribute(mm_kernel, cudaFuncAttributeMaxDynamicSharedMemorySize, GEMM_SMEM);
    cudaFuncSetAttribute(trans_kernel, cudaFuncAttributeMaxDynamicSharedMemorySize,
                         (2 * KK * ADIM) * (int)sizeof(float));
    cudaFuncSetAttribute(scan_kernel, cudaFuncAttributeMaxDynamicSharedMemorySize,
                         (KK * KK + LDUR * KK + 2 * KK) * (int)sizeof(float));

    split_kernel<<<2048, 256>>>(uniqenc, (__nv_bfloat16*)p_uh, (__nv_bfloat16*)p_ul, (size_t)BSZ * TH2);
    {   dim3 g(8192 / 64, 1024 / 64);
        transpose_split_kernel<<<g, 256>>>(W_c1, (__nv_bfloat16*)p_w1h, (__nv_bfloat16*)p_w1l, 1024, 8192); }
    {   dim3 g(16384 / 64, 8192 / 64);
        transpose_split_kernel<<<g, 256>>>(W_c2, (__nv_bfloat16*)p_w2h, (__nv_bfloat16*)p_w2l, 8192, 16384); }
    pi_kernel<<<BSZ, 128>>>(uniqenc, W_init, b_init, p_pi);
    tsc_kernel<<<KK, 128>>>(A_from, A_to, p_tsc);

    // h = relu(uniq @ W1 + b1), split -> hh/hl.  M=1024, N=8192, K=1024
    {   dim3 g(1024 / BM, 8192 / BN);
        mm_kernel<<<g, 256, GEMM_SMEM>>>(
            (const __nv_bfloat16*)p_uh, (const __nv_bfloat16*)p_ul,
            (const __nv_bfloat16*)p_w1h, (const __nv_bfloat16*)p_w1l,
            b_c1, nullptr, (__nv_bfloat16*)p_hh, (__nv_bfloat16*)p_hl, 8192, 1024, 1); }
    // cond = h @ W2 + b2.  M=1024, N=16384, K=8192
    {   dim3 g(1024 / BM, 16384 / BN);
        mm_kernel<<<g, 256, GEMM_SMEM>>>(
            (const __nv_bfloat16*)p_hh, (const __nv_bfloat16*)p_hl,
            (const __nv_bfloat16*)p_w2h, (const __nv_bfloat16*)p_w2l,
            b_c2, p_cond, nullptr, nullptr, 16384, 8192, 0); }

    trans_kernel<<<BSZ, 256, (2 * KK * ADIM) * sizeof(float)>>>(p_cond, p_tsc, p_P);
    scan_kernel<<<BSZ, 128, (KK * KK + LDUR * KK + 2 * KK) * sizeof(float)>>>(obs_lps, p_pi, p_P, out);

    (void)in_sizes; (void)n_in; (void)out_size;
}

// round 16
// speedup vs baseline: 4.1180x; 1.2493x over previous
#include <cuda_runtime.h>
#include <cuda_fp16.h>
#include <math.h>
#include <stdint.h>

#define KK 128
#define ADIM 64
#define LDUR 6
#define TT 60
#define BSZ 1024
#define TH2 1024
#define NEGINF -1e38f

// ---- HMMA GEMM tiling (fp16 2-pass: Ah,Al split + Bh single) ----
#define BM 128
#define BN 128
#define BKT 32            // k per stage (fp16 elems)
#define ROWB 80           // padded smem row bytes (32 halves -> 40 halves)
#define MATB (BM * ROWB)  // 10240 bytes per matrix tile
#define STGB (3 * MATB)   // Ah, Al, Bh
#define NSTG 4
#define GEMM_SMEM (NSTG * STGB)   // 122880

#define PI_SMEM ((1024 * 17 + 16 * 128) * 4)   // 77824

// ---------------- scratch (static device, no allocations) ----------------
__device__ __align__(16) __half g_uh[(size_t)BSZ * TH2];
__device__ __align__(16) __half g_ul[(size_t)BSZ * TH2];
__device__ __align__(16) __half g_w1h[(size_t)8192 * 1024];
__device__ __align__(16) __half g_w2h[(size_t)16384 * 8192];
__device__ __align__(16) __half g_hh[(size_t)BSZ * 8192];
__device__ __align__(16) __half g_hl[(size_t)BSZ * 8192];
__device__ float g_cond[(size_t)BSZ * (KK * ADIM * 2)];
__device__ float g_pi[BSZ * KK];
__device__ float g_tsc[KK * KK];
__device__ float g_P[(size_t)BSZ * KK * KK];

__device__ __forceinline__ uint32_t smem_u32(const void* p) {
    uint32_t a;
    asm("{ .reg .u64 t; cvta.to.shared.u64 t, %1; cvt.u32.u64 %0, t; }" : "=r"(a) : "l"(p));
    return a;
}
#define CPASYNC16(sa, ga) \
    asm volatile("cp.async.cg.shared.global [%0], [%1], 16;" :: "r"(sa), "l"(ga) : "memory")
#define CPCOMMIT() asm volatile("cp.async.commit_group;" ::: "memory")
#define CPWAIT2()  asm volatile("cp.async.wait_group 2;" ::: "memory")

__device__ __forceinline__ void ldsm4(uint32_t* r, uint32_t a) {
    asm volatile("ldmatrix.sync.aligned.m8n8.x4.shared.b16 {%0,%1,%2,%3}, [%4];"
        : "=r"(r[0]), "=r"(r[1]), "=r"(r[2]), "=r"(r[3]) : "r"(a));
}
__device__ __forceinline__ void mma16816(float* d, const uint32_t* a, const uint32_t* b) {
    asm volatile("mma.sync.aligned.m16n8k16.row.col.f32.f16.f16.f32 "
        "{%0,%1,%2,%3}, {%4,%5,%6,%7}, {%8,%9}, {%0,%1,%2,%3};"
        : "+f"(d[0]), "+f"(d[1]), "+f"(d[2]), "+f"(d[3])
        : "r"(a[0]), "r"(a[1]), "r"(a[2]), "r"(a[3]), "r"(b[0]), "r"(b[1]));
}

// ---------------- prep: fp32 -> fp16 hi/lo split ----------------
__global__ __launch_bounds__(256) void split_kernel(
    const float* __restrict__ in, __half* __restrict__ hi,
    __half* __restrict__ lo, size_t n)
{
    size_t i = (size_t)blockIdx.x * 256 + threadIdx.x;
    size_t st = (size_t)gridDim.x * 256;
    for (; i < n; i += st) {
        float v = in[i];
        __half h = __float2half_rn(v);
        hi[i] = h;
        lo[i] = __float2half_rn(v - __half2float(h));
    }
}

// fp32 [R][C] -> fp16 [C][R] (hi only)
__global__ __launch_bounds__(256) void transpose_half_kernel(
    const float* __restrict__ in, __half* __restrict__ hi, int R, int C)
{
    __shared__ float t[64][65];
    int tx = threadIdx.x & 63, ty = threadIdx.x >> 6;
    int c0 = blockIdx.x * 64, r0 = blockIdx.y * 64;
    for (int r = ty; r < 64; r += 4) t[r][tx] = in[(size_t)(r0 + r) * C + c0 + tx];
    __syncthreads();
    for (int r = ty; r < 64; r += 4)
        hi[(size_t)(c0 + r) * R + r0 + tx] = __float2half_rn(t[tx][r]);
}

// ---------------- HMMA GEMM: D[M,N] = A @ B^T, fp16 2-pass (A hi/lo, B hi) ----------------
// A: [M][Kd] fp16 hi/lo.  B: [N][Kd] fp16 (i.e. W^T).
// grid = (M/128, N/128), 256 threads. relu_split: out = relu(D+bias) -> fp16 hi/lo.
__global__ __launch_bounds__(256, 1) void mm_kernel(
    const __half* __restrict__ Agh, const __half* __restrict__ Agl,
    const __half* __restrict__ Bgh,
    const float* __restrict__ bias, float* __restrict__ out_f32,
    __half* __restrict__ out_hi, __half* __restrict__ out_lo,
    int Nout, int Kd, int relu_split)
{
    extern __shared__ __align__(16) char smem[];
    const uint32_t sb0 = smem_u32(smem);
    const int tid = threadIdx.x, lane = tid & 31, wid = tid >> 5;
    const int wm = wid >> 1, wn = wid & 1;
    const int m0 = blockIdx.x * BM, n0 = blockIdx.y * BN;
    const int NC = Kd / BKT;

    const __half* pAh = Agh + (size_t)m0 * Kd;
    const __half* pAl = Agl + (size_t)m0 * Kd;
    const __half* pBh = Bgh + (size_t)n0 * Kd;

    const int li0 = tid * 2;

    auto load_stage = [&](int c) {
        if (c < NC) {
            uint32_t sb = sb0 + (c % NSTG) * STGB;
            int k0 = c * BKT;
#pragma unroll
            for (int ii = 0; ii < 2; ii++) {
                int i = li0 + ii;
                int row = i >> 2, ch = i & 3;
                size_t go = (size_t)row * Kd + k0 + ch * 8;
                uint32_t so = (uint32_t)(row * ROWB + ch * 16);
                CPASYNC16(sb + so,            pAh + go);
                CPASYNC16(sb + MATB + so,     pAl + go);
                CPASYNC16(sb + 2 * MATB + so, pBh + go);
            }
        }
        CPCOMMIT();   // unconditional: keeps group accounting aligned at the tail
    };

    float acc[2][8][4];
#pragma unroll
    for (int mt = 0; mt < 2; mt++)
#pragma unroll
        for (int nt = 0; nt < 8; nt++)
#pragma unroll
            for (int r = 0; r < 4; r++) acc[mt][nt][r] = 0.f;

    // A: x4 -> (rows0-7,k0-7),(rows8-15,k0-7),(rows0-7,k8-15),(rows8-15,k8-15)
    const uint32_t aoff = (uint32_t)((wm * 32 + (lane & 15)) * ROWB + (lane >> 4) * 16);
    // B (non-trans): n-rows; (n0-7,k0-7),(n0-7,k8-15),(n8-15,k0-7),(n8-15,k8-15)
    const uint32_t boff = (uint32_t)((wn * 64 + (lane & 7) + ((lane >> 4) & 1) * 8) * ROWB
                                     + ((lane >> 3) & 1) * 16);

    load_stage(0);
    load_stage(1);
    load_stage(2);

    for (int c = 0; c < NC; c++) {
        CPWAIT2();          // stage c resident
        __syncthreads();    // everyone done with stage that slot (c+3)%4 overwrites
        load_stage(c + 3);

        uint32_t sb = sb0 + (c % NSTG) * STGB;
#pragma unroll
        for (int kk = 0; kk < 2; kk++) {
            uint32_t ah[2][4], al[2][4], bh[8][2];
#pragma unroll
            for (int mt = 0; mt < 2; mt++) {
                ldsm4(ah[mt], sb + aoff + mt * (16 * ROWB) + kk * 32);
                ldsm4(al[mt], sb + MATB + aoff + mt * (16 * ROWB) + kk * 32);
            }
#pragma unroll
            for (int np = 0; np < 4; np++) {
                uint32_t r[4];
                ldsm4(r, sb + 2 * MATB + boff + np * (16 * ROWB) + kk * 32);
                bh[2 * np][0] = r[0]; bh[2 * np][1] = r[1];
                bh[2 * np + 1][0] = r[2]; bh[2 * np + 1][1] = r[3];
            }
#pragma unroll
            for (int mt = 0; mt < 2; mt++)
#pragma unroll
                for (int nt = 0; nt < 8; nt++) {
                    mma16816(acc[mt][nt], ah[mt], bh[nt]);
                    mma16816(acc[mt][nt], al[mt], bh[nt]);
                }
        }
        __syncthreads();
    }

    // epilogue
#pragma unroll
    for (int mt = 0; mt < 2; mt++) {
        int mrow = m0 + wm * 32 + mt * 16 + (lane >> 2);
#pragma unroll
        for (int nt = 0; nt < 8; nt++) {
            int n = n0 + wn * 64 + nt * 8 + (lane & 3) * 2;
            float b0 = bias[n], b1 = bias[n + 1];
            float v0 = acc[mt][nt][0] + b0, v1 = acc[mt][nt][1] + b1;
            float v2 = acc[mt][nt][2] + b0, v3 = acc[mt][nt][3] + b1;
            if (!relu_split) {
                *(float2*)(out_f32 + (size_t)mrow * Nout + n)       = make_float2(v0, v1);
                *(float2*)(out_f32 + (size_t)(mrow + 8) * Nout + n) = make_float2(v2, v3);
            } else {
                v0 = fmaxf(v0, 0.f); v1 = fmaxf(v1, 0.f);
                v2 = fmaxf(v2, 0.f); v3 = fmaxf(v3, 0.f);
                __half h0 = __float2half_rn(v0), h1 = __float2half_rn(v1);
                __half h2 = __float2half_rn(v2), h3 = __float2half_rn(v3);
                __half2 hv0; hv0.x = h0; hv0.y = h1;
                __half2 hv1; hv1.x = h2; hv1.y = h3;
                __half2 lv0, lv1;
                lv0.x = __float2half_rn(v0 - __half2float(h0));
                lv0.y = __float2half_rn(v1 - __half2float(h1));
                lv1.x = __float2half_rn(v2 - __half2float(h2));
                lv1.y = __float2half_rn(v3 - __half2float(h3));
                *(__half2*)(out_hi + (size_t)mrow * Nout + n)       = hv0;
                *(__half2*)(out_lo + (size_t)mrow * Nout + n)       = lv0;
                *(__half2*)(out_hi + (size_t)(mrow + 8) * Nout + n) = hv1;
                *(__half2*)(out_lo + (size_t)(mrow + 8) * Nout + n) = lv1;
            }
        }
    }
}

// ---------------- pi = log_softmax(uniqenc @ W_init + b), 16 rows/block ----------------
__global__ __launch_bounds__(256) void pi_kernel(
    const float* __restrict__ uniq, const float* __restrict__ W,
    const float* __restrict__ b, float* __restrict__ pi)
{
    extern __shared__ float ps[];
    float* us = ps;                 // [1024][17] padded
    float* sc = ps + 1024 * 17;     // [16][128]
    int r0 = blockIdx.x * 16, tid = threadIdx.x;
    for (int idx = tid; idx < 16 * 1024; idx += 256) {
        int r = idx >> 10, i = idx & 1023;
        us[i * 17 + r] = uniq[(size_t)(r0 + r) * TH2 + i];
    }
    __syncthreads();
    int r = tid >> 4;            // 0..15
    int k0 = (tid & 15) * 8;     // 0..120
    float acc[8];
#pragma unroll
    for (int q = 0; q < 8; q++) acc[q] = 0.f;
#pragma unroll 4
    for (int i = 0; i < 1024; i++) {
        float u = us[i * 17 + r];
        float4 w0 = *(const float4*)&W[i * KK + k0];
        float4 w1 = *(const float4*)&W[i * KK + k0 + 4];
        acc[0] += u * w0.x; acc[1] += u * w0.y; acc[2] += u * w0.z; acc[3] += u * w0.w;
        acc[4] += u * w1.x; acc[5] += u * w1.y; acc[6] += u * w1.z; acc[7] += u * w1.w;
    }
#pragma unroll
    for (int q = 0; q < 8; q++) sc[r * KK + k0 + q] = acc[q] + b[k0 + q];
    __syncthreads();
    int wid = tid >> 5, lane = tid & 31;
    for (int rr = wid; rr < 16; rr += 8) {
        float v[4]; float m = -INFINITY;
#pragma unroll
        for (int q = 0; q < 4; q++) { v[q] = sc[rr * KK + lane + q * 32]; m = fmaxf(m, v[q]); }
#pragma unroll
        for (int off = 16; off; off >>= 1) m = fmaxf(m, __shfl_xor_sync(0xffffffffu, m, off));
        float s = 0.f;
#pragma unroll
        for (int q = 0; q < 4; q++) s += expf(v[q] - m);
#pragma unroll
        for (int off = 16; off; off >>= 1) s += __shfl_xor_sync(0xffffffffu, s, off);
        float lse = m + logf(s);
#pragma unroll
        for (int q = 0; q < 4; q++)
            pi[(size_t)(r0 + rr) * KK + lane + q * 32] = v[q] - lse;
    }
}

__global__ __launch_bounds__(128) void tsc_kernel(
    const float* __restrict__ Af, const float* __restrict__ At, float* __restrict__ tsc)
{
    int k = blockIdx.x, j = threadIdx.x;
    float acc = 0.f;
#pragma unroll
    for (int a = 0; a < ADIM; a++) acc += Af[k * ADIM + a] * At[a * KK + j];
    if (k == j) acc += NEGINF;
    tsc[k * KK + j] = acc;
}

// ---------------- trans -> P (softmax probabilities) ----------------
__global__ __launch_bounds__(256) void trans_kernel(
    const float* __restrict__ cond, const float* __restrict__ tsc, float* __restrict__ P)
{
    extern __shared__ float sm[];
    float* fr = sm;
    float* to = sm + KK * ADIM;
    float* tr = sm;
    int b = blockIdx.x, tid = threadIdx.x;
    const float* cb = cond + (size_t)b * KK * 2 * ADIM;
    for (int idx = tid; idx < KK * 2 * ADIM; idx += 256) {
        int kk = idx >> 7, a = idx & 127;
        float v = cb[idx];
        if (a < ADIM) fr[kk * ADIM + a] = v;
        else          to[kk * ADIM + (a - ADIM)] = v;
    }
    __syncthreads();
    int tx = tid & 15, ty = tid >> 4;
    float acc[8][8];
#pragma unroll
    for (int i = 0; i < 8; i++)
#pragma unroll
        for (int j = 0; j < 8; j++) acc[i][j] = 0.f;
#pragma unroll 4
    for (int a = 0; a < ADIM; a++) {
        float ra[8], rb[8];
#pragma unroll
        for (int i = 0; i < 8; i++) ra[i] = fr[(ty * 8 + i) * ADIM + a];
#pragma unroll
        for (int j = 0; j < 8; j++) rb[j] = to[(tx * 8 + j) * ADIM + a];
#pragma unroll
        for (int i = 0; i < 8; i++)
#pragma unroll
            for (int j = 0; j < 8; j++) acc[i][j] += ra[i] * rb[j];
    }
    __syncthreads();
#pragma unroll
    for (int i = 0; i < 8; i++)
#pragma unroll
        for (int j = 0; j < 8; j++)
            tr[(ty * 8 + i) * KK + tx * 8 + j] = acc[i][j] + tsc[(ty * 8 + i) * KK + tx * 8 + j];
    __syncthreads();
    int wid = tid >> 5, lane = tid & 31;
    for (int row = wid; row < KK; row += 8) {
        float v[4]; float m = -INFINITY;
#pragma unroll
        for (int i = 0; i < 4; i++) { v[i] = tr[row * KK + lane + i * 32]; m = fmaxf(m, v[i]); }
#pragma unroll
        for (int off = 16; off; off >>= 1) m = fmaxf(m, __shfl_xor_sync(0xffffffffu, m, off));
        float e[4]; float s = 0.f;
#pragma unroll
        for (int i = 0; i < 4; i++) { e[i] = expf(v[i] - m); s += e[i]; }
#pragma unroll
        for (int off = 16; off; off >>= 1) s += __shfl_xor_sync(0xffffffffu, s, off);
        float inv = 1.0f / s;
#pragma unroll
        for (int i = 0; i < 4; i++)
            P[(size_t)b * KK * KK + row * KK + lane + i * 32] = e[i] * inv;
    }
}

// ---------------- scan ----------------
__global__ __launch_bounds__(128) void scan_kernel(
    const float* __restrict__ obs, const float* __restrict__ pi,
    const float* __restrict__ Pg, float* __restrict__ out)
{
    extern __shared__ float sm[];
    float* Psm  = sm;
    float* buf  = sm + KK * KK;
    float* pvec = buf + LDUR * KK;
    float* red  = pvec + KK;
    int b = blockIdx.x, j = threadIdx.x;
    const float len_lp = -1.7917594692280550f;
    {
        const float4* src = (const float4*)(Pg + (size_t)b * KK * KK);
        float4* dst = (float4*)Psm;
        for (int i = j; i < KK * KK / 4; i += 128) dst[i] = src[i];
    }
    buf[j] = pi[b * KK + j];
#pragma unroll
    for (int l = 1; l < LDUR; l++) buf[l * KK + j] = NEGINF;
    __syncthreads();
    int base = 0;
    for (int t = 0; t < TT; t++) {
        float vs[LDUR], vmax = -INFINITY;
#pragma unroll
        for (int l = 0; l < LDUR; l++) {
            int st = t - l;
            float v = NEGINF;
            if (st >= 0)
                v = buf[((base + l) % LDUR) * KK + j] + obs[(((size_t)l * TT + st) * BSZ + b) * KK + j] + len_lp;
            vs[l] = v; vmax = fmaxf(vmax, v);
        }
        float alpha;
        if (vmax < -1e30f) alpha = NEGINF;
        else {
            float s = 0.f;
#pragma unroll
            for (int l = 0; l < LDUR; l++) s += expf(vs[l] - vmax);
            alpha = vmax + logf(s);
        }
        red[j] = alpha; __syncthreads();
        for (int s2 = 64; s2; s2 >>= 1) { if (j < s2) red[j] = fmaxf(red[j], red[j + s2]); __syncthreads(); }
        float M = red[0];
        __syncthreads();
        pvec[j] = expf(alpha - M);
        __syncthreads();
        if (t == TT - 1) {
            red[j] = pvec[j]; __syncthreads();
            for (int s2 = 64; s2; s2 >>= 1) { if (j < s2) red[j] += red[j + s2]; __syncthreads(); }
            if (j == 0) out[b] = M + logf(red[0]);
            break;
        }
        float a0 = 0.f, a1 = 0.f, a2 = 0.f, a3 = 0.f;
#pragma unroll 8
        for (int kk = 0; kk < KK; kk += 4) {
            a0 += pvec[kk + 0] * Psm[(kk + 0) * KK + j];
            a1 += pvec[kk + 1] * Psm[(kk + 1) * KK + j];
            a2 += pvec[kk + 2] * Psm[(kk + 2) * KK + j];
            a3 += pvec[kk + 3] * Psm[(kk + 3) * KK + j];
        }
        float astar = M + logf((a0 + a1) + (a2 + a3));
        base = (base + LDUR - 1) % LDUR;
        buf[base * KK + j] = astar;
        __syncthreads();
    }
}

// ---------------- launch ----------------
extern "C" void kernel_launch(void* const* d_in, const int* in_sizes, int n_in,
                              void* d_out, int out_size)
{
    const float* uniqenc = (const float*)d_in[0];
    const float* obs_lps = (const float*)d_in[1];
    const float* W_init  = (const float*)d_in[2];
    const float* b_init  = (const float*)d_in[3];
    const float* A_from  = (const float*)d_in[4];
    const float* A_to    = (const float*)d_in[5];
    const float* W_c1    = (const float*)d_in[6];
    const float* b_c1    = (const float*)d_in[7];
    const float* W_c2    = (const float*)d_in[8];
    const float* b_c2    = (const float*)d_in[9];
    float* out = (float*)d_out;

    void *p_uh, *p_ul, *p_w1h, *p_w2h, *p_hh, *p_hl;
    float *p_cond, *p_pi, *p_tsc, *p_P;
    cudaGetSymbolAddress(&p_uh, g_uh);   cudaGetSymbolAddress(&p_ul, g_ul);
    cudaGetSymbolAddress(&p_w1h, g_w1h); cudaGetSymbolAddress(&p_w2h, g_w2h);
    cudaGetSymbolAddress(&p_hh, g_hh);   cudaGetSymbolAddress(&p_hl, g_hl);
    cudaGetSymbolAddress((void**)&p_cond, g_cond);
    cudaGetSymbolAddress((void**)&p_pi, g_pi);
    cudaGetSymbolAddress((void**)&p_tsc, g_tsc);
    cudaGetSymbolAddress((void**)&p_P, g_P);

    cudaFuncSetAttribute(mm_kernel, cudaFuncAttributeMaxDynamicSharedMemorySize, GEMM_SMEM);
    cudaFuncSetAttribute(pi_kernel, cudaFuncAttributeMaxDynamicSharedMemorySize, PI_SMEM);
    cudaFuncSetAttribute(trans_kernel, cudaFuncAttributeMaxDynamicSharedMemorySize,
                         (2 * KK * ADIM) * (int)sizeof(float));
    cudaFuncSetAttribute(scan_kernel, cudaFuncAttributeMaxDynamicSharedMemorySize,
                         (KK * KK + LDUR * KK + 2 * KK) * (int)sizeof(float));

    split_kernel<<<2048, 256>>>(uniqenc, (__half*)p_uh, (__half*)p_ul, (size_t)BSZ * TH2);
    {   dim3 g(8192 / 64, 1024 / 64);
        transpose_half_kernel<<<g, 256>>>(W_c1, (__half*)p_w1h, 1024, 8192); }
    {   dim3 g(16384 / 64, 8192 / 64);
        transpose_half_kernel<<<g, 256>>>(W_c2, (__half*)p_w2h, 8192, 16384); }
    pi_kernel<<<BSZ / 16, 256, PI_SMEM>>>(uniqenc, W_init, b_init, p_pi);
    tsc_kernel<<<KK, 128>>>(A_from, A_to, p_tsc);

    // h = relu(uniq @ W1 + b1), split -> hh/hl.  M=1024, N=8192, K=1024
    {   dim3 g(1024 / BM, 8192 / BN);
        mm_kernel<<<g, 256, GEMM_SMEM>>>(
            (const __half*)p_uh, (const __half*)p_ul, (const __half*)p_w1h,
            b_c1, nullptr, (__half*)p_hh, (__half*)p_hl, 8192, 1024, 1); }
    // cond = h @ W2 + b2.  M=1024, N=16384, K=8192
    {   dim3 g(1024 / BM, 16384 / BN);
        mm_kernel<<<g, 256, GEMM_SMEM>>>(
            (const __half*)p_hh, (const __half*)p_hl, (const __half*)p_w2h,
            b_c2, p_cond, nullptr, nullptr, 16384, 8192, 0); }

    trans_kernel<<<BSZ, 256, (2 * KK * ADIM) * sizeof(float)>>>(p_cond, p_tsc, p_P);
    scan_kernel<<<BSZ, 128, (KK * KK + LDUR * KK + 2 * KK) * sizeof(float)>>>(obs_lps, p_pi, p_P, out);

    (void)in_sizes; (void)n_in; (void)out_size;
}